// round 13
// baseline (speedup 1.0000x reference)
#include <cuda_runtime.h>
#include <cuda_fp16.h>
#include <cstdint>

#define BB 16
#define QL 16
#define DD 256
#define NH 4
#define HD 64
#define PLEN 512
#define GLEN 16384
#define MAXS 64
#define GM (BB * GLEN)      // 262144
#define PM (BB * PLEN)      // 8192

// ------------------------- scratch (device globals) -------------------------
__device__ __half g_kh_g[(size_t)GM * DD];
__device__ __half g_vh_g[(size_t)GM * DD];
__device__ __half g_kh_p[PM * DD];
__device__ __half g_vh_p[PM * DD];
__device__ __half g_wkv_h[2][512 * DD];
__device__ float g_mem[2][BB * QL * DD];
__device__ float g_hq[BB * QL * DD];
__device__ float g_vec[BB * QL * DD];
__device__ float g_ao[BB * QL * DD];
__device__ float g_pacc[(size_t)BB * NH * MAXS * QL * HD];
__device__ float g_pm[BB * NH * MAXS * QL];
__device__ float g_pl[BB * NH * MAXS * QL];

// ------------------------- fast exp on FMA pipe -----------------------------
__device__ __forceinline__ float fexp(float x) {
    float y = x * 1.4426950408889634f;
    y = fmaxf(y, -125.0f);
    float n = rintf(y);
    float f = y - n;
    float p = 1.3333558146e-3f;
    p = fmaf(p, f, 9.6181291076e-3f);
    p = fmaf(p, f, 5.5504108664e-2f);
    p = fmaf(p, f, 2.4022650696e-1f);
    p = fmaf(p, f, 6.9314718056e-1f);
    p = fmaf(p, f, 1.0f);
    return __int_as_float(((int)n + 127) << 23) * p;
}

// ------------------------- mma / smem / cp.async helpers --------------------
__device__ __forceinline__ uint32_t smem_u32(const void* p) {
    uint32_t a;
    asm("{ .reg .u64 t; cvta.to.shared.u64 t, %1; cvt.u32.u64 %0, t; }" : "=r"(a) : "l"(p));
    return a;
}
__device__ __forceinline__ void ldm_x4(uint32_t* r, uint32_t addr) {
    asm volatile("ldmatrix.sync.aligned.m8n8.x4.shared.b16 {%0,%1,%2,%3}, [%4];"
                 : "=r"(r[0]), "=r"(r[1]), "=r"(r[2]), "=r"(r[3]) : "r"(addr));
}
__device__ __forceinline__ void ldm_x4_t(uint32_t* r, uint32_t addr) {
    asm volatile("ldmatrix.sync.aligned.m8n8.x4.trans.shared.b16 {%0,%1,%2,%3}, [%4];"
                 : "=r"(r[0]), "=r"(r[1]), "=r"(r[2]), "=r"(r[3]) : "r"(addr));
}
__device__ __forceinline__ void mma16(float* c, const uint32_t* a, const uint32_t* b) {
    asm volatile(
        "mma.sync.aligned.m16n8k16.row.col.f32.f16.f16.f32 "
        "{%0,%1,%2,%3}, {%4,%5,%6,%7}, {%8,%9}, {%0,%1,%2,%3};"
        : "+f"(c[0]), "+f"(c[1]), "+f"(c[2]), "+f"(c[3])
        : "r"(a[0]), "r"(a[1]), "r"(a[2]), "r"(a[3]), "r"(b[0]), "r"(b[1]));
}
__device__ __forceinline__ void cp_a16(uint32_t s, const void* g) {
    asm volatile("cp.async.cg.shared.global [%0], [%1], 16;" :: "r"(s), "l"(g));
}
#define CP_COMMIT() asm volatile("cp.async.commit_group;" ::: "memory")
#define CP_WAIT0()  asm volatile("cp.async.wait_group 0;" ::: "memory")
#define CP_WAIT1()  asm volatile("cp.async.wait_group 1;" ::: "memory")

__device__ __forceinline__ uint32_t packh2(float a, float b) {
    __half2 h = __floats2half2_rn(a, b);
    return *(uint32_t*)&h;
}

// ------------------------- weight convert (transposed, concat K|V) ----------
__global__ void __launch_bounds__(256) split_wkv(const float* __restrict__ Wk,
                                                 const float* __restrict__ Wv,
                                                 __half* __restrict__ Th) {
    int n = blockIdx.x, k = threadIdx.x;
    const float* W = (n < 256) ? Wk : Wv;
    Th[(size_t)n * DD + k] = __float2half_rn(W[(size_t)k * DD + (n & 255)]);
}

// ------- mma GEMM v4: A-panel resident, N-loop in block, cp.async B ---------
#define A_BYTES 65536
#define BSTG 10240
#define KV_SMEM (A_BYTES + 2 * BSTG)   // 86016

__global__ void __launch_bounds__(256) gemm_kv(
    const float* __restrict__ X, const __half* __restrict__ Bhp,
    __half* __restrict__ Kh, __half* __restrict__ Vh) {
    extern __shared__ char smk[];
    uint32_t uA = smem_u32(smk);
    uint32_t uB = uA + A_BYTES;

    int t = threadIdx.x;
    int wid = t >> 5, lane = t & 31;
    int wm = (wid & 3) * 32;
    int wn = (wid >> 2) * 64;
    size_t m0 = (size_t)blockIdx.x * 128;
    int q = lane >> 3, r8 = lane & 7;

#pragma unroll 8
    for (int u = 0; u < 32; u++) {
        int f = t + 256 * u;
        int row = f >> 6, c = f & 63;
        float4 v = *(const float4*)(X + (m0 + row) * DD + c * 4);
        uint32_t off = row * 512 + (((c >> 1) ^ (row & 7)) << 4) + (c & 1) * 8;
        *(uint2*)(smk + off) = make_uint2(packh2(v.x, v.y), packh2(v.z, v.w));
    }
    __syncthreads();

    for (int nb = 0; nb < 4; nb++) {
        int n0 = nb * 128;
        float acc[2][8][4];
#pragma unroll
        for (int i = 0; i < 2; i++)
#pragma unroll
            for (int j = 0; j < 8; j++)
#pragma unroll
                for (int e = 0; e < 4; e++) acc[i][j][e] = 0.f;

#pragma unroll
        for (int u = 0; u < 2; u++) {
            int f = t + 256 * u;
            int row = f >> 2, c = f & 3;
            cp_a16(uB + row * 80 + c * 16, Bhp + (size_t)(n0 + row) * DD + c * 8);
        }
        CP_COMMIT();

        for (int c = 0; c < 8; c++) {
            uint32_t curB = uB + (c & 1) * BSTG;
            __syncthreads();
            if (c + 1 < 8) {
                int k0n = (c + 1) * 32;
                uint32_t nxtB = uB + ((c + 1) & 1) * BSTG;
#pragma unroll
                for (int u = 0; u < 2; u++) {
                    int f = t + 256 * u;
                    int row = f >> 2, cc = f & 3;
                    cp_a16(nxtB + row * 80 + cc * 16,
                           Bhp + (size_t)(n0 + row) * DD + k0n + cc * 8);
                }
                CP_COMMIT();
                CP_WAIT1();
            } else {
                CP_WAIT0();
            }
            __syncthreads();

            int k0 = c * 32;
#pragma unroll
            for (int s = 0; s < 2; s++) {
                int kk = k0 + s * 16;
                uint32_t aH[2][4], bH[8][2];
#pragma unroll
                for (int i = 0; i < 2; i++) {
                    int row = wm + i * 16 + (q & 1) * 8 + r8;
                    int col = kk + (q >> 1) * 8;
                    uint32_t off = row * 512 + ((((uint32_t)col >> 3) ^ (row & 7)) << 4);
                    ldm_x4(aH[i], uA + off);
                }
#pragma unroll
                for (int p = 0; p < 4; p++) {
                    int n = wn + p * 16 + (q >> 1) * 8 + r8;
                    int col = s * 16 + (q & 1) * 8;
                    uint32_t rh[4];
                    ldm_x4(rh, curB + (uint32_t)(n * 40 + col) * 2);
                    bH[2 * p][0] = rh[0]; bH[2 * p][1] = rh[1];
                    bH[2 * p + 1][0] = rh[2]; bH[2 * p + 1][1] = rh[3];
                }
#pragma unroll
                for (int i = 0; i < 2; i++)
#pragma unroll
                    for (int j = 0; j < 8; j++)
                        mma16(acc[i][j], aH[i], bH[j]);
            }
        }

        __half* Dst = (n0 < 256) ? Kh : Vh;
        int cbase = n0 & 255;
#pragma unroll
        for (int i = 0; i < 2; i++) {
            int r0 = wm + i * 16 + (lane >> 2);
#pragma unroll
            for (int j = 0; j < 8; j++) {
                int cc = cbase + wn + j * 8 + (lane & 3) * 2;
                *(uint32_t*)(Dst + (m0 + r0) * DD + cc) = packh2(acc[i][j][0], acc[i][j][1]);
                *(uint32_t*)(Dst + (m0 + r0 + 8) * DD + cc) = packh2(acc[i][j][2], acc[i][j][3]);
            }
        }
    }
}

// ------------------------- mean pooling: graph -> mem0 ----------------------
__global__ void __launch_bounds__(256) pool_kernel(const float* __restrict__ graph,
                                                   float* __restrict__ mem0) {
    int bm = blockIdx.x;
    int d = threadIdx.x;
    const float* src = graph + (size_t)bm * 1024 * DD + d;
    float s0 = 0.f, s1 = 0.f, s2 = 0.f, s3 = 0.f;
    for (int r = 0; r < 1024; r += 4) {
        s0 += src[(size_t)(r + 0) * DD];
        s1 += src[(size_t)(r + 1) * DD];
        s2 += src[(size_t)(r + 2) * DD];
        s3 += src[(size_t)(r + 3) * DD];
    }
    mem0[(size_t)bm * DD + d] = (s0 + s1 + s2 + s3) * (1.0f / 1024.0f);
}

// ---------------- small GEMM: O[256,256] = X @ W, grid (16,16) --------------
__global__ void __launch_bounds__(256) gemm_small(const float* __restrict__ X,
                                                  const float* __restrict__ W,
                                                  float* __restrict__ O) {
    __shared__ float Xs[16][256];
    int t = threadIdx.x;
    int r0 = blockIdx.y * 16, n0 = blockIdx.x * 16;
#pragma unroll
    for (int u = 0; u < 4; u++) {
        int f = t + 256 * u;
        int row = f >> 6, c4 = (f & 63) << 2;
        *(float4*)&Xs[row][c4] = *(const float4*)(X + (size_t)(r0 + row) * DD + c4);
    }
    __syncthreads();
    int col = n0 + (t & 15), lr = t >> 4;
    float a0 = 0.f, a1 = 0.f, a2 = 0.f, a3 = 0.f;
#pragma unroll 8
    for (int k = 0; k < 256; k += 4) {
        a0 = fmaf(Xs[lr][k + 0], W[(size_t)(k + 0) * DD + col], a0);
        a1 = fmaf(Xs[lr][k + 1], W[(size_t)(k + 1) * DD + col], a1);
        a2 = fmaf(Xs[lr][k + 2], W[(size_t)(k + 2) * DD + col], a2);
        a3 = fmaf(Xs[lr][k + 3], W[(size_t)(k + 3) * DD + col], a3);
    }
    O[(size_t)(r0 + lr) * DD + col] = (a0 + a1) + (a2 + a3);
}

// --- flash attention v7: warp-autonomous split-K, register softmax ----------
// Each warp owns 16 keys per 128-key tile; per-warp online softmax in regs;
// per-warp partial output -> split slot (split*8 + warp). Only 2 syncs/tile.
#define STAGE_BYTES 32768
#define ATT_SMEM (65536 + 4352)

__global__ void __launch_bounds__(256) attn_tc5(
    const float* __restrict__ hq,
    const __half* __restrict__ Kh, const __half* __restrict__ Vh,
    const int* __restrict__ mask, int klen, int kps) {
    extern __shared__ char sm[];
    float* Qst = (float*)(sm + 65536);
    uint32_t uBase = smem_u32(sm);

    int t = threadIdx.x;
    int w = t >> 5, lane = t & 31;
    int g = lane >> 2, tig = lane & 3;
    int q2 = lane >> 3, r8 = lane & 7;
    int split = blockIdx.x, h = blockIdx.y, b = blockIdx.z;
    int key0 = split * kps;
    int ntiles = kps >> 7;

    // stage Q (16x64 fp32)
    {
        int r = t >> 4, c4 = (t & 15) << 2;
        *(float4*)&Qst[r * 64 + c4] =
            *(const float4*)(hq + (size_t)(b * QL + r) * DD + h * HD + c4);
    }
    __syncthreads();

#define LOAD_TILE(k0_, stg_) do {                                               \
    _Pragma("unroll")                                                           \
    for (int pl_ = 0; pl_ < 2; pl_++) {                                         \
        const __half* Gp_ = (pl_ == 0) ? Kh : Vh;                               \
        uint32_t sb_ = (stg_) + pl_ * 16384;                                    \
        _Pragma("unroll")                                                       \
        for (int u_ = 0; u_ < 4; u_++) {                                        \
            int f_ = t + 256 * u_;                                              \
            int row_ = f_ >> 3, ch_ = f_ & 7;                                   \
            const char* gp_ = (const char*)(Gp_ +                               \
                ((size_t)b * klen + (k0_) + row_) * DD + h * HD) + ch_ * 16;    \
            uint32_t sa_ = sb_ + row_ * 128 + (((ch_ ^ (row_ & 7))) << 4);      \
            cp_a16(sa_, gp_);                                                   \
        }                                                                       \
    }                                                                           \
} while (0)

    LOAD_TILE(key0, uBase);
    CP_COMMIT();

    // Q fragments (single fp16 plane), 4 k-steps
    uint32_t qh[4][4];
#pragma unroll
    for (int s = 0; s < 4; s++) {
        int cb = s * 16 + tig * 2;
        qh[s][0] = packh2(Qst[g * 64 + cb], Qst[g * 64 + cb + 1]);
        qh[s][1] = packh2(Qst[(g + 8) * 64 + cb], Qst[(g + 8) * 64 + cb + 1]);
        qh[s][2] = packh2(Qst[g * 64 + cb + 8], Qst[g * 64 + cb + 9]);
        qh[s][3] = packh2(Qst[(g + 8) * 64 + cb + 8], Qst[(g + 8) * 64 + cb + 9]);
    }

    float accP[8][4];
#pragma unroll
    for (int j = 0; j < 8; j++)
#pragma unroll
        for (int e = 0; e < 4; e++) accP[j][e] = 0.f;
    float M0 = -3e38f, M1 = -3e38f, L0 = 0.f, L1 = 0.f;

    for (int kt = 0; kt < ntiles; kt++) {
        uint32_t stage = uBase + (kt & 1) * STAGE_BYTES;
        int k0 = key0 + (kt << 7);
        __syncthreads();                 // all warps done reading alt stage
        if (kt + 1 < ntiles) {
            LOAD_TILE(k0 + 128, uBase + ((kt + 1) & 1) * STAGE_BYTES);
            CP_COMMIT();
            CP_WAIT1();
        } else {
            CP_WAIT0();
        }
        __syncthreads();                 // tile kt visible

        // masks for this warp's 16 keys (4 per thread)
        const int* mb = mask + (size_t)b * klen + k0 + w * 16;
        int mk0 = __ldg(mb + tig * 2);
        int mk1 = __ldg(mb + tig * 2 + 1);
        int mk2 = __ldg(mb + 8 + tig * 2);
        int mk3 = __ldg(mb + 9 + tig * 2);

        // ---- QK: warp w covers keys [w*16, w*16+16) ----
        float c2[2][4];
#pragma unroll
        for (int j = 0; j < 2; j++)
#pragma unroll
            for (int e = 0; e < 4; e++) c2[j][e] = 0.f;
#pragma unroll
        for (int s = 0; s < 4; s++) {
            int row = w * 16 + (q2 >> 1) * 8 + r8;
            int ch = s * 2 + (q2 & 1);
            uint32_t off = stage + row * 128 + ((ch ^ (row & 7)) << 4);
            uint32_t rh[4];
            ldm_x4(rh, off);
            uint32_t b0h[2] = {rh[0], rh[1]}, b1h[2] = {rh[2], rh[3]};
            mma16(c2[0], qh[s], b0h);
            mma16(c2[1], qh[s], b1h);
        }

        // ---- per-warp register softmax (reduce over tig group) ----
        float svg[4], svh[4];
        svg[0] = mk0 ? c2[0][0] * 0.125f : -1e30f;
        svg[1] = mk1 ? c2[0][1] * 0.125f : -1e30f;
        svg[2] = mk2 ? c2[1][0] * 0.125f : -1e30f;
        svg[3] = mk3 ? c2[1][1] * 0.125f : -1e30f;
        svh[0] = mk0 ? c2[0][2] * 0.125f : -1e30f;
        svh[1] = mk1 ? c2[0][3] * 0.125f : -1e30f;
        svh[2] = mk2 ? c2[1][2] * 0.125f : -1e30f;
        svh[3] = mk3 ? c2[1][3] * 0.125f : -1e30f;

        float mg = fmaxf(fmaxf(svg[0], svg[1]), fmaxf(svg[2], svg[3]));
        float mh = fmaxf(fmaxf(svh[0], svh[1]), fmaxf(svh[2], svh[3]));
        mg = fmaxf(mg, __shfl_xor_sync(~0u, mg, 1));
        mg = fmaxf(mg, __shfl_xor_sync(~0u, mg, 2));
        mh = fmaxf(mh, __shfl_xor_sync(~0u, mh, 1));
        mh = fmaxf(mh, __shfl_xor_sync(~0u, mh, 2));

        float n0 = fmaxf(M0, mg), n1 = fmaxf(M1, mh);
        float pg[4], ph[4];
#pragma unroll
        for (int i = 0; i < 4; i++) {
            pg[i] = fexp(svg[i] - n0);   // masked vals -> ~2e-38, fp16 -> 0
            ph[i] = fexp(svh[i] - n1);
        }
        float lg = (pg[0] + pg[1]) + (pg[2] + pg[3]);
        float lh = (ph[0] + ph[1]) + (ph[2] + ph[3]);
        lg += __shfl_xor_sync(~0u, lg, 1);
        lg += __shfl_xor_sync(~0u, lg, 2);
        lh += __shfl_xor_sync(~0u, lh, 1);
        lh += __shfl_xor_sync(~0u, lh, 2);

        float sc0 = fexp(M0 - n0), sc1 = fexp(M1 - n1);
        L0 = L0 * sc0 + lg; M0 = n0;
        L1 = L1 * sc1 + lh; M1 = n1;
#pragma unroll
        for (int j = 0; j < 8; j++) {
            accP[j][0] *= sc0; accP[j][1] *= sc0;
            accP[j][2] *= sc1; accP[j][3] *= sc1;
        }

        // scores -> P A-fragment (register repack, no smem)
        uint32_t ap[4];
        ap[0] = packh2(pg[0], pg[1]);
        ap[1] = packh2(ph[0], ph[1]);
        ap[2] = packh2(pg[2], pg[3]);
        ap[3] = packh2(ph[2], ph[3]);

        // ---- PV: P[16x16] @ V[16keys x 64dims] ----
#pragma unroll
        for (int nb = 0; nb < 4; nb++) {
            int vrow = w * 16 + (q2 & 1) * 8 + r8;
            int chv = nb * 2 + (q2 >> 1);
            uint32_t voff = stage + 16384 + vrow * 128 + ((chv ^ (vrow & 7)) << 4);
            uint32_t v4[4];
            ldm_x4_t(v4, voff);
            uint32_t b0[2] = {v4[0], v4[1]}, b1[2] = {v4[2], v4[3]};
            mma16(accP[nb * 2], ap, b0);
            mma16(accP[nb * 2 + 1], ap, b1);
        }
    }

    // ---- per-warp partial output to split slot (split*8 + w) ----
    size_t pbase = ((size_t)(b * NH + h) * MAXS + split * 8 + w) * QL;
    float* pa = g_pacc + pbase * HD;
#pragma unroll
    for (int nb = 0; nb < 8; nb++) {
        int cc = nb * 8 + tig * 2;
        *(float2*)(pa + (size_t)g * HD + cc) = make_float2(accP[nb][0], accP[nb][1]);
        *(float2*)(pa + (size_t)(g + 8) * HD + cc) = make_float2(accP[nb][2], accP[nb][3]);
    }
    if (tig == 0) {
        g_pm[pbase + g] = M0;
        g_pm[pbase + g + 8] = M1;
        g_pl[pbase + g] = L0;
        g_pl[pbase + g + 8] = L1;
    }
}

// ------------------------- merge split-K partials ---------------------------
__global__ void __launch_bounds__(256) attn_merge(float* __restrict__ vec, int nsplit) {
    __shared__ float w[MAXS][16];
    __shared__ float invL[16];
    int t = threadIdx.x;
    int h = blockIdx.x, b = blockIdx.y;
    size_t base = (size_t)(b * NH + h) * MAXS * QL;
    if (t < 16) {
        float M = -3e38f;
        for (int s = 0; s < nsplit; s++) M = fmaxf(M, g_pm[base + s * QL + t]);
        float L = 0.f;
        for (int s = 0; s < nsplit; s++) {
            float ww = fexp(g_pm[base + s * QL + t] - M);
            w[s][t] = ww;
            L += g_pl[base + s * QL + t] * ww;
        }
        invL[t] = 1.f / L;
    }
    __syncthreads();
    int r = t >> 4, c4 = (t & 15) << 2;
    float ox = 0.f, oy = 0.f, oz = 0.f, ow = 0.f;
    for (int s = 0; s < nsplit; s++) {
        float ww = w[s][r];
        float4 a = *(const float4*)(g_pacc + (base + s * QL + r) * HD + c4);
        ox = fmaf(a.x, ww, ox); oy = fmaf(a.y, ww, oy);
        oz = fmaf(a.z, ww, oz); ow = fmaf(a.w, ww, ow);
    }
    float il = invL[r];
    *(float4*)(vec + (size_t)(b * QL + r) * DD + h * HD + c4) =
        make_float4(ox * il, oy * il, oz * il, ow * il);
}

// ------------------------- gate + residual ----------------------------------
__global__ void __launch_bounds__(256) gate_kernel(
    const float* __restrict__ mem, const float* __restrict__ ao,
    const float* __restrict__ Wg, const float* __restrict__ bg,
    float* __restrict__ out) {
    __shared__ float xs[512];
    int row = blockIdx.x;
    int c = threadIdx.x;
    xs[c] = mem[(size_t)row * DD + c];
    xs[256 + c] = ao[(size_t)row * DD + c];
    __syncthreads();
    float s0 = 0.f, s1 = 0.f, s2 = 0.f, s3 = 0.f;
#pragma unroll 4
    for (int k = 0; k < 512; k += 4) {
        float4 x = *(float4*)&xs[k];
        s0 = fmaf(x.x, Wg[(size_t)(k + 0) * DD + c], s0);
        s1 = fmaf(x.y, Wg[(size_t)(k + 1) * DD + c], s1);
        s2 = fmaf(x.z, Wg[(size_t)(k + 2) * DD + c], s2);
        s3 = fmaf(x.w, Wg[(size_t)(k + 3) * DD + c], s3);
    }
    float sum = (s0 + s1) + (s2 + s3) + bg[c];
    float gate = 1.f / (1.f + fexp(-sum));
    out[(size_t)row * DD + c] = gate * xs[c] + (1.f - gate) * xs[256 + c];
}

// ------------------------- launch -------------------------------------------
extern "C" void kernel_launch(void* const* d_in, const int* in_sizes, int n_in,
                              void* d_out, int out_size) {
    const float* pattern = (const float*)d_in[0];
    const float* graph = (const float*)d_in[1];
    const int* pmask = (const int*)d_in[2];
    const int* gmask = (const int*)d_in[3];
    const float* pW[6];
    const float* gW[6];
    for (int i = 0; i < 6; i++) pW[i] = (const float*)d_in[4 + i];
    for (int i = 0; i < 6; i++) gW[i] = (const float*)d_in[10 + i];
    float* out = (float*)d_out;

    float *memb, *hq, *vec, *ao;
    __half *khg, *vhg, *khp, *vhp, *wh;
    cudaGetSymbolAddress((void**)&memb, g_mem);
    cudaGetSymbolAddress((void**)&hq, g_hq);
    cudaGetSymbolAddress((void**)&vec, g_vec);
    cudaGetSymbolAddress((void**)&ao, g_ao);
    cudaGetSymbolAddress((void**)&khg, g_kh_g);
    cudaGetSymbolAddress((void**)&vhg, g_vh_g);
    cudaGetSymbolAddress((void**)&khp, g_kh_p);
    cudaGetSymbolAddress((void**)&vhp, g_vh_p);
    cudaGetSymbolAddress((void**)&wh, g_wkv_h);
    float* mem0 = memb;
    float* mem1 = memb + BB * QL * DD;

    cudaFuncSetAttribute(attn_tc5, cudaFuncAttributeMaxDynamicSharedMemorySize,
                         ATT_SMEM);
    cudaFuncSetAttribute(gemm_kv, cudaFuncAttributeMaxDynamicSharedMemorySize,
                         KV_SMEM);

    pool_kernel<<<256, 256>>>(graph, mem0);                               // 1
    split_wkv<<<512, 256>>>(gW[1], gW[2], wh + 512 * DD);                 // 2
    split_wkv<<<512, 256>>>(pW[1], pW[2], wh);                            // 3
    gemm_kv<<<GM / 128, 256, KV_SMEM>>>(graph, wh + 512 * DD, khg, vhg);  // 4 (profiled)
    gemm_kv<<<PM / 128, 256, KV_SMEM>>>(pattern, wh, khp, vhp);           // 5

    float* cur = mem0;
    float* other = mem1;
    for (int it = 0; it < 3; it++) {
        for (int ph = 0; ph < 2; ph++) {
            const float* const* W = ph ? gW : pW;
            const __half* kh = ph ? khg : khp;
            const __half* vh = ph ? vhg : vhp;
            const int* mask = ph ? gmask : pmask;
            int klen = ph ? GLEN : PLEN;
            int splits = ph ? 8 : 4;
            int kps = klen / splits;

            gemm_small<<<dim3(16, 16), 256>>>(cur, W[0], hq);
            attn_tc5<<<dim3(splits, NH, BB), 256, ATT_SMEM>>>(hq, kh, vh,
                                                              mask, klen, kps);
            attn_merge<<<dim3(NH, BB), 256>>>(vec, splits * 8);
            gemm_small<<<dim3(16, 16), 256>>>(vec, W[3], ao);

            bool last = (it == 2 && ph == 1);
            float* dst = last ? out : other;
            gate_kernel<<<256, 256>>>(cur, ao, W[4], W[5], dst);
            other = cur;
            cur = dst;
        }
    }
}

// round 14
// speedup vs baseline: 1.0147x; 1.0147x over previous
#include <cuda_runtime.h>
#include <cuda_fp16.h>
#include <cstdint>

#define BB 16
#define QL 16
#define DD 256
#define NH 4
#define HD 64
#define PLEN 512
#define GLEN 16384
#define MAXS 32
#define GM (BB * GLEN)      // 262144
#define PM (BB * PLEN)      // 8192
#define SSTR 132

// ---------------- scratch (device globals; K/V are 4 head-major planes) -----
__device__ __half g_kh_g[(size_t)GM * DD];
__device__ __half g_vh_g[(size_t)GM * DD];
__device__ __half g_kh_p[PM * DD];
__device__ __half g_vh_p[PM * DD];
__device__ __half g_wkv_h[2][512 * DD];
__device__ float g_mem[2][BB * QL * DD];
__device__ float g_hq[BB * QL * DD];
__device__ float g_vec[BB * QL * DD];
__device__ float g_ao[BB * QL * DD];
__device__ float g_pacc[BB * NH * MAXS * QL * HD];
__device__ float g_pm[BB * NH * MAXS * QL];
__device__ float g_pl[BB * NH * MAXS * QL];

// ------------------------- fast exp on FMA pipe -----------------------------
__device__ __forceinline__ float fexp(float x) {
    float y = x * 1.4426950408889634f;
    y = fmaxf(y, -125.0f);
    float n = rintf(y);
    float f = y - n;
    float p = 1.3333558146e-3f;
    p = fmaf(p, f, 9.6181291076e-3f);
    p = fmaf(p, f, 5.5504108664e-2f);
    p = fmaf(p, f, 2.4022650696e-1f);
    p = fmaf(p, f, 6.9314718056e-1f);
    p = fmaf(p, f, 1.0f);
    return __int_as_float(((int)n + 127) << 23) * p;
}

// ------------------------- mma / smem / cp.async helpers --------------------
__device__ __forceinline__ uint32_t smem_u32(const void* p) {
    uint32_t a;
    asm("{ .reg .u64 t; cvta.to.shared.u64 t, %1; cvt.u32.u64 %0, t; }" : "=r"(a) : "l"(p));
    return a;
}
__device__ __forceinline__ void ldm_x4(uint32_t* r, uint32_t addr) {
    asm volatile("ldmatrix.sync.aligned.m8n8.x4.shared.b16 {%0,%1,%2,%3}, [%4];"
                 : "=r"(r[0]), "=r"(r[1]), "=r"(r[2]), "=r"(r[3]) : "r"(addr));
}
__device__ __forceinline__ void ldm_x4_t(uint32_t* r, uint32_t addr) {
    asm volatile("ldmatrix.sync.aligned.m8n8.x4.trans.shared.b16 {%0,%1,%2,%3}, [%4];"
                 : "=r"(r[0]), "=r"(r[1]), "=r"(r[2]), "=r"(r[3]) : "r"(addr));
}
__device__ __forceinline__ void mma16(float* c, const uint32_t* a, const uint32_t* b) {
    asm volatile(
        "mma.sync.aligned.m16n8k16.row.col.f32.f16.f16.f32 "
        "{%0,%1,%2,%3}, {%4,%5,%6,%7}, {%8,%9}, {%0,%1,%2,%3};"
        : "+f"(c[0]), "+f"(c[1]), "+f"(c[2]), "+f"(c[3])
        : "r"(a[0]), "r"(a[1]), "r"(a[2]), "r"(a[3]), "r"(b[0]), "r"(b[1]));
}
__device__ __forceinline__ void cp_a16(uint32_t s, const void* g) {
    asm volatile("cp.async.cg.shared.global [%0], [%1], 16;" :: "r"(s), "l"(g));
}
#define CP_COMMIT() asm volatile("cp.async.commit_group;" ::: "memory")
#define CP_WAIT0()  asm volatile("cp.async.wait_group 0;" ::: "memory")
#define CP_WAIT1()  asm volatile("cp.async.wait_group 1;" ::: "memory")

__device__ __forceinline__ uint32_t packh2(float a, float b) {
    __half2 h = __floats2half2_rn(a, b);
    return *(uint32_t*)&h;
}

// ------------------------- weight convert (transposed, concat K|V) ----------
__global__ void __launch_bounds__(256) split_wkv(const float* __restrict__ Wk,
                                                 const float* __restrict__ Wv,
                                                 __half* __restrict__ Th) {
    int n = blockIdx.x, k = threadIdx.x;
    const float* W = (n < 256) ? Wk : Wv;
    Th[(size_t)n * DD + k] = __float2half_rn(W[(size_t)k * DD + (n & 255)]);
}

// ------- mma GEMM v4: A-panel resident, N-loop in block, cp.async B ---------
// Epilogue writes head-major planes: dst[(head*Mrows + m)*64 + d].
#define A_BYTES 65536
#define BSTG 10240
#define KV_SMEM (A_BYTES + 2 * BSTG)   // 86016

__global__ void __launch_bounds__(256) gemm_kv(
    const float* __restrict__ X, const __half* __restrict__ Bhp,
    __half* __restrict__ Kh, __half* __restrict__ Vh, int Mrows) {
    extern __shared__ char smk[];
    uint32_t uA = smem_u32(smk);
    uint32_t uB = uA + A_BYTES;

    int t = threadIdx.x;
    int wid = t >> 5, lane = t & 31;
    int wm = (wid & 3) * 32;
    int wn = (wid >> 2) * 64;
    size_t m0 = (size_t)blockIdx.x * 128;
    int q = lane >> 3, r8 = lane & 7;

#pragma unroll 8
    for (int u = 0; u < 32; u++) {
        int f = t + 256 * u;
        int row = f >> 6, c = f & 63;
        float4 v = *(const float4*)(X + (m0 + row) * DD + c * 4);
        uint32_t off = row * 512 + (((c >> 1) ^ (row & 7)) << 4) + (c & 1) * 8;
        *(uint2*)(smk + off) = make_uint2(packh2(v.x, v.y), packh2(v.z, v.w));
    }
    __syncthreads();

    for (int nb = 0; nb < 4; nb++) {
        int n0 = nb * 128;
        float acc[2][8][4];
#pragma unroll
        for (int i = 0; i < 2; i++)
#pragma unroll
            for (int j = 0; j < 8; j++)
#pragma unroll
                for (int e = 0; e < 4; e++) acc[i][j][e] = 0.f;

#pragma unroll
        for (int u = 0; u < 2; u++) {
            int f = t + 256 * u;
            int row = f >> 2, c = f & 3;
            cp_a16(uB + row * 80 + c * 16, Bhp + (size_t)(n0 + row) * DD + c * 8);
        }
        CP_COMMIT();

        for (int c = 0; c < 8; c++) {
            uint32_t curB = uB + (c & 1) * BSTG;
            __syncthreads();
            if (c + 1 < 8) {
                int k0n = (c + 1) * 32;
                uint32_t nxtB = uB + ((c + 1) & 1) * BSTG;
#pragma unroll
                for (int u = 0; u < 2; u++) {
                    int f = t + 256 * u;
                    int row = f >> 2, cc = f & 3;
                    cp_a16(nxtB + row * 80 + cc * 16,
                           Bhp + (size_t)(n0 + row) * DD + k0n + cc * 8);
                }
                CP_COMMIT();
                CP_WAIT1();
            } else {
                CP_WAIT0();
            }
            __syncthreads();

            int k0 = c * 32;
#pragma unroll
            for (int s = 0; s < 2; s++) {
                int kk = k0 + s * 16;
                uint32_t aH[2][4], bH[8][2];
#pragma unroll
                for (int i = 0; i < 2; i++) {
                    int row = wm + i * 16 + (q & 1) * 8 + r8;
                    int col = kk + (q >> 1) * 8;
                    uint32_t off = row * 512 + ((((uint32_t)col >> 3) ^ (row & 7)) << 4);
                    ldm_x4(aH[i], uA + off);
                }
#pragma unroll
                for (int p = 0; p < 4; p++) {
                    int n = wn + p * 16 + (q >> 1) * 8 + r8;
                    int col = s * 16 + (q & 1) * 8;
                    uint32_t rh[4];
                    ldm_x4(rh, curB + (uint32_t)(n * 40 + col) * 2);
                    bH[2 * p][0] = rh[0]; bH[2 * p][1] = rh[1];
                    bH[2 * p + 1][0] = rh[2]; bH[2 * p + 1][1] = rh[3];
                }
#pragma unroll
                for (int i = 0; i < 2; i++)
#pragma unroll
                    for (int j = 0; j < 8; j++)
                        mma16(acc[i][j], aH[i], bH[j]);
            }
        }

        __half* Dst = (n0 < 256) ? Kh : Vh;
        int cbase = n0 & 255;
#pragma unroll
        for (int i = 0; i < 2; i++) {
            int r0 = wm + i * 16 + (lane >> 2);
#pragma unroll
            for (int j = 0; j < 8; j++) {
                int cc = cbase + wn + j * 8 + (lane & 3) * 2;
                __half* dp = Dst + ((size_t)(cc >> 6) * Mrows + (m0 + r0)) * HD + (cc & 63);
                *(uint32_t*)dp = packh2(acc[i][j][0], acc[i][j][1]);
                *(uint32_t*)(dp + 8 * HD) = packh2(acc[i][j][2], acc[i][j][3]);
            }
        }
    }
}

// ------------------------- mean pooling: graph -> mem0 ----------------------
__global__ void __launch_bounds__(256) pool_kernel(const float* __restrict__ graph,
                                                   float* __restrict__ mem0) {
    int bm = blockIdx.x;
    int d = threadIdx.x;
    const float* src = graph + (size_t)bm * 1024 * DD + d;
    float s0 = 0.f, s1 = 0.f, s2 = 0.f, s3 = 0.f;
    for (int r = 0; r < 1024; r += 4) {
        s0 += src[(size_t)(r + 0) * DD];
        s1 += src[(size_t)(r + 1) * DD];
        s2 += src[(size_t)(r + 2) * DD];
        s3 += src[(size_t)(r + 3) * DD];
    }
    mem0[(size_t)bm * DD + d] = (s0 + s1 + s2 + s3) * (1.0f / 1024.0f);
}

// ---------------- small GEMM: O[256,256] = X @ W, grid (16,16) --------------
__global__ void __launch_bounds__(256) gemm_small(const float* __restrict__ X,
                                                  const float* __restrict__ W,
                                                  float* __restrict__ O) {
    __shared__ float Xs[16][256];
    int t = threadIdx.x;
    int r0 = blockIdx.y * 16, n0 = blockIdx.x * 16;
#pragma unroll
    for (int u = 0; u < 4; u++) {
        int f = t + 256 * u;
        int row = f >> 6, c4 = (f & 63) << 2;
        *(float4*)&Xs[row][c4] = *(const float4*)(X + (size_t)(r0 + row) * DD + c4);
    }
    __syncthreads();
    int col = n0 + (t & 15), lr = t >> 4;
    float a0 = 0.f, a1 = 0.f, a2 = 0.f, a3 = 0.f;
#pragma unroll 8
    for (int k = 0; k < 256; k += 4) {
        a0 = fmaf(Xs[lr][k + 0], W[(size_t)(k + 0) * DD + col], a0);
        a1 = fmaf(Xs[lr][k + 1], W[(size_t)(k + 1) * DD + col], a1);
        a2 = fmaf(Xs[lr][k + 2], W[(size_t)(k + 2) * DD + col], a2);
        a3 = fmaf(Xs[lr][k + 3], W[(size_t)(k + 3) * DD + col], a3);
    }
    O[(size_t)(r0 + lr) * DD + col] = (a0 + a1) + (a2 + a3);
}

// ------ flash attention v6h: head-major K/V planes, cp.async 2-stage --------
#define STAGE_BYTES 32768
#define ATT_SMEM 74688

__global__ void __launch_bounds__(256) attn_tc4(
    const float* __restrict__ hq,
    const __half* __restrict__ Kh, const __half* __restrict__ Vh,
    const int* __restrict__ mask, int klen, int kps) {
    extern __shared__ char sm[];
    float* Sst = (float*)(sm + 65536);
    float* rowM = (float*)(sm + 73984);
    float* rowL = (float*)(sm + 74048);
    float* rowS = (float*)(sm + 74112);
    int* mk = (int*)(sm + 74176);
    uint32_t uBase = smem_u32(sm);

    int t = threadIdx.x;
    int w = t >> 5, lane = t & 31;
    int g = lane >> 2, tig = lane & 3;
    int q2 = lane >> 3, r8 = lane & 7;
    int split = blockIdx.x, h = blockIdx.y, b = blockIdx.z;
    int key0 = split * kps;
    int ntiles = kps >> 7;
    size_t prow = ((size_t)(h * BB + b)) * klen;   // row base in head plane

    {
        int r = t >> 4, c4 = (t & 15) << 2;
        *(float4*)&Sst[r * 64 + c4] =
            *(const float4*)(hq + (size_t)(b * QL + r) * DD + h * HD + c4);
    }
    if (t < 16) { rowM[t] = -3e38f; rowL[t] = 0.f; rowS[t] = 0.f; }
    __syncthreads();

#define LOAD_TILE(k0_, stg_) do {                                               \
    _Pragma("unroll")                                                           \
    for (int pl_ = 0; pl_ < 2; pl_++) {                                         \
        const __half* Gp_ = (pl_ == 0) ? Kh : Vh;                               \
        uint32_t sb_ = (stg_) + pl_ * 16384;                                    \
        _Pragma("unroll")                                                       \
        for (int u_ = 0; u_ < 4; u_++) {                                        \
            int f_ = t + 256 * u_;                                              \
            int row_ = f_ >> 3, ch_ = f_ & 7;                                   \
            const char* gp_ = (const char*)(Gp_ +                               \
                (prow + (k0_) + row_) * HD) + ch_ * 16;                         \
            uint32_t sa_ = sb_ + row_ * 128 + (((ch_ ^ (row_ & 7))) << 4);      \
            cp_a16(sa_, gp_);                                                   \
        }                                                                       \
    }                                                                           \
} while (0)

    LOAD_TILE(key0, uBase);
    CP_COMMIT();

    // Q fragments: single fp16 plane
    uint32_t qh[4][4];
#pragma unroll
    for (int s = 0; s < 4; s++) {
        int cb = s * 16 + tig * 2;
        qh[s][0] = packh2(Sst[g * 64 + cb], Sst[g * 64 + cb + 1]);
        qh[s][1] = packh2(Sst[(g + 8) * 64 + cb], Sst[(g + 8) * 64 + cb + 1]);
        qh[s][2] = packh2(Sst[g * 64 + cb + 8], Sst[g * 64 + cb + 9]);
        qh[s][3] = packh2(Sst[(g + 8) * 64 + cb + 8], Sst[(g + 8) * 64 + cb + 9]);
    }

    float acc[4] = {0.f, 0.f, 0.f, 0.f};
    uint32_t* SW = (uint32_t*)Sst;

    for (int kt = 0; kt < ntiles; kt++) {
        uint32_t stage = uBase + (kt & 1) * STAGE_BYTES;
        int k0 = key0 + (kt << 7);
        __syncthreads();
        if (kt + 1 < ntiles) {
            LOAD_TILE(k0 + 128, uBase + ((kt + 1) & 1) * STAGE_BYTES);
            CP_COMMIT();
            CP_WAIT1();
        } else {
            CP_WAIT0();
        }
        __syncthreads();
        if (t < 128) mk[t] = mask[(size_t)b * klen + k0 + t];

        // ---- QK (1-pass): warp w covers keys [w*16, w*16+16) ----
        float c2[2][4];
#pragma unroll
        for (int j = 0; j < 2; j++)
#pragma unroll
            for (int e = 0; e < 4; e++) c2[j][e] = 0.f;
#pragma unroll
        for (int s = 0; s < 4; s++) {
            int row = w * 16 + (q2 >> 1) * 8 + r8;
            int ch = s * 2 + (q2 & 1);
            uint32_t off = stage + row * 128 + ((ch ^ (row & 7)) << 4);
            uint32_t rh[4];
            ldm_x4(rh, off);
            uint32_t b0h[2] = {rh[0], rh[1]}, b1h[2] = {rh[2], rh[3]};
            mma16(c2[0], qh[s], b0h);
            mma16(c2[1], qh[s], b1h);
        }
#pragma unroll
        for (int j = 0; j < 2; j++) {
            int kc = w * 16 + j * 8 + tig * 2;
            Sst[g * SSTR + kc] = c2[j][0] * 0.125f;
            Sst[g * SSTR + kc + 1] = c2[j][1] * 0.125f;
            Sst[(g + 8) * SSTR + kc] = c2[j][2] * 0.125f;
            Sst[(g + 8) * SSTR + kc + 1] = c2[j][3] * 0.125f;
        }
        __syncthreads();

        // ---- online softmax; pack P fp16 pairs (even words) ----
        {
            int row = t >> 4, sub = t & 15;
            int cb = sub * 8;
            float sv[8];
#pragma unroll
            for (int i = 0; i < 8; i++) sv[i] = Sst[row * SSTR + cb + i];
            float lmax = -3e38f;
#pragma unroll
            for (int i = 0; i < 8; i++)
                if (mk[cb + i]) lmax = fmaxf(lmax, sv[i]);
#pragma unroll
            for (int o = 8; o; o >>= 1) lmax = fmaxf(lmax, __shfl_xor_sync(~0u, lmax, o));
            float oldm = rowM[row];
            float newm = fmaxf(oldm, lmax);
            float pv[8];
            float lsum = 0.f;
#pragma unroll
            for (int i = 0; i < 8; i++) {
                pv[i] = mk[cb + i] ? fexp(sv[i] - newm) : 0.f;
                lsum += pv[i];
            }
#pragma unroll
            for (int o = 8; o; o >>= 1) lsum += __shfl_xor_sync(~0u, lsum, o);
            if (sub == 0) {
                float sc = fexp(oldm - newm);
                rowS[row] = sc;
                rowL[row] = rowL[row] * sc + lsum;
                rowM[row] = newm;
            }
#pragma unroll
            for (int i = 0; i < 8; i += 2)
                SW[row * SSTR + cb + i] = packh2(pv[i], pv[i + 1]);
        }
        __syncthreads();

        // ---- PV (1-pass): warp w covers dims [w*8, w*8+8) ----
        {
            float s0 = rowS[g], s1 = rowS[g + 8];
            acc[0] *= s0; acc[1] *= s0; acc[2] *= s1; acc[3] *= s1;
#pragma unroll
            for (int kb = 0; kb < 4; kb++) {
                int vrow = kb * 32 + q2 * 8 + r8;
                uint32_t voff = stage + 16384 + vrow * 128 + ((w ^ (vrow & 7)) << 4);
                uint32_t v4[4];
                ldm_x4_t(v4, voff);
#pragma unroll
                for (int kh2 = 0; kh2 < 2; kh2++) {
                    int kk = kb * 32 + kh2 * 16;
                    uint32_t ah[4] = {SW[g * SSTR + kk + tig * 2],
                                      SW[(g + 8) * SSTR + kk + tig * 2],
                                      SW[g * SSTR + kk + 8 + tig * 2],
                                      SW[(g + 8) * SSTR + kk + 8 + tig * 2]};
                    uint32_t bh[2] = {v4[2 * kh2], v4[2 * kh2 + 1]};
                    mma16(acc, ah, bh);
                }
            }
        }
    }
    size_t pbase = ((size_t)(b * NH + h) * MAXS + split) * QL;
    float* pa = g_pacc + pbase * HD;
    int cc = w * 8 + tig * 2;
    *(float2*)(pa + (size_t)g * HD + cc) = make_float2(acc[0], acc[1]);
    *(float2*)(pa + (size_t)(g + 8) * HD + cc) = make_float2(acc[2], acc[3]);
    if (t < 16) { g_pm[pbase + t] = rowM[t]; g_pl[pbase + t] = rowL[t]; }
}

// ------------------------- merge split-K partials ---------------------------
__global__ void __launch_bounds__(256) attn_merge(float* __restrict__ vec, int nsplit) {
    __shared__ float w[MAXS][16];
    __shared__ float invL[16];
    int t = threadIdx.x;
    int h = blockIdx.x, b = blockIdx.y;
    size_t base = (size_t)(b * NH + h) * MAXS * QL;
    if (t < 16) {
        float M = -3e38f;
        for (int s = 0; s < nsplit; s++) M = fmaxf(M, g_pm[base + s * QL + t]);
        float L = 0.f;
        for (int s = 0; s < nsplit; s++) {
            float ww = fexp(g_pm[base + s * QL + t] - M);
            w[s][t] = ww;
            L += g_pl[base + s * QL + t] * ww;
        }
        invL[t] = 1.f / L;
    }
    __syncthreads();
    int r = t >> 4, c4 = (t & 15) << 2;
    float ox = 0.f, oy = 0.f, oz = 0.f, ow = 0.f;
    for (int s = 0; s < nsplit; s++) {
        float ww = w[s][r];
        float4 a = *(const float4*)(g_pacc + (base + s * QL + r) * HD + c4);
        ox = fmaf(a.x, ww, ox); oy = fmaf(a.y, ww, oy);
        oz = fmaf(a.z, ww, oz); ow = fmaf(a.w, ww, ow);
    }
    float il = invL[r];
    *(float4*)(vec + (size_t)(b * QL + r) * DD + h * HD + c4) =
        make_float4(ox * il, oy * il, oz * il, ow * il);
}

// ------------------------- gate + residual ----------------------------------
__global__ void __launch_bounds__(256) gate_kernel(
    const float* __restrict__ mem, const float* __restrict__ ao,
    const float* __restrict__ Wg, const float* __restrict__ bg,
    float* __restrict__ out) {
    __shared__ float xs[512];
    int row = blockIdx.x;
    int c = threadIdx.x;
    xs[c] = mem[(size_t)row * DD + c];
    xs[256 + c] = ao[(size_t)row * DD + c];
    __syncthreads();
    float s0 = 0.f, s1 = 0.f, s2 = 0.f, s3 = 0.f;
#pragma unroll 4
    for (int k = 0; k < 512; k += 4) {
        float4 x = *(float4*)&xs[k];
        s0 = fmaf(x.x, Wg[(size_t)(k + 0) * DD + c], s0);
        s1 = fmaf(x.y, Wg[(size_t)(k + 1) * DD + c], s1);
        s2 = fmaf(x.z, Wg[(size_t)(k + 2) * DD + c], s2);
        s3 = fmaf(x.w, Wg[(size_t)(k + 3) * DD + c], s3);
    }
    float sum = (s0 + s1) + (s2 + s3) + bg[c];
    float gate = 1.f / (1.f + fexp(-sum));
    out[(size_t)row * DD + c] = gate * xs[c] + (1.f - gate) * xs[256 + c];
}

// ------------------------- launch -------------------------------------------
extern "C" void kernel_launch(void* const* d_in, const int* in_sizes, int n_in,
                              void* d_out, int out_size) {
    const float* pattern = (const float*)d_in[0];
    const float* graph = (const float*)d_in[1];
    const int* pmask = (const int*)d_in[2];
    const int* gmask = (const int*)d_in[3];
    const float* pW[6];
    const float* gW[6];
    for (int i = 0; i < 6; i++) pW[i] = (const float*)d_in[4 + i];
    for (int i = 0; i < 6; i++) gW[i] = (const float*)d_in[10 + i];
    float* out = (float*)d_out;

    float *memb, *hq, *vec, *ao;
    __half *khg, *vhg, *khp, *vhp, *wh;
    cudaGetSymbolAddress((void**)&memb, g_mem);
    cudaGetSymbolAddress((void**)&hq, g_hq);
    cudaGetSymbolAddress((void**)&vec, g_vec);
    cudaGetSymbolAddress((void**)&ao, g_ao);
    cudaGetSymbolAddress((void**)&khg, g_kh_g);
    cudaGetSymbolAddress((void**)&vhg, g_vh_g);
    cudaGetSymbolAddress((void**)&khp, g_kh_p);
    cudaGetSymbolAddress((void**)&vhp, g_vh_p);
    cudaGetSymbolAddress((void**)&wh, g_wkv_h);
    float* mem0 = memb;
    float* mem1 = memb + BB * QL * DD;

    cudaFuncSetAttribute(attn_tc4, cudaFuncAttributeMaxDynamicSharedMemorySize,
                         ATT_SMEM);
    cudaFuncSetAttribute(gemm_kv, cudaFuncAttributeMaxDynamicSharedMemorySize,
                         KV_SMEM);

    pool_kernel<<<256, 256>>>(graph, mem0);                                   // 1
    split_wkv<<<512, 256>>>(gW[1], gW[2], wh + 512 * DD);                     // 2
    split_wkv<<<512, 256>>>(pW[1], pW[2], wh);                                // 3
    gemm_kv<<<GM / 128, 256, KV_SMEM>>>(graph, wh + 512 * DD, khg, vhg, GM);  // 4 (profiled)
    gemm_kv<<<PM / 128, 256, KV_SMEM>>>(pattern, wh, khp, vhp, PM);           // 5

    float* cur = mem0;
    float* other = mem1;
    for (int it = 0; it < 3; it++) {
        for (int ph = 0; ph < 2; ph++) {
            const float* const* W = ph ? gW : pW;
            const __half* kh = ph ? khg : khp;
            const __half* vh = ph ? vhg : vhp;
            const int* mask = ph ? gmask : pmask;
            int klen = ph ? GLEN : PLEN;
            int splits = ph ? 16 : 4;
            int kps = klen / splits;

            gemm_small<<<dim3(16, 16), 256>>>(cur, W[0], hq);
            attn_tc4<<<dim3(splits, NH, BB), 256, ATT_SMEM>>>(hq, kh, vh,
                                                              mask, klen, kps);
            attn_merge<<<dim3(NH, BB), 256>>>(vec, splits);
            gemm_small<<<dim3(16, 16), 256>>>(vec, W[3], ao);

            bool last = (it == 2 && ph == 1);
            float* dst = last ? out : other;
            gate_kernel<<<256, 256>>>(cur, ao, W[4], W[5], dst);
            other = cur;
            cur = dst;
        }
    }
}

// round 15
// speedup vs baseline: 1.0534x; 1.0381x over previous
#include <cuda_runtime.h>
#include <cuda_fp16.h>
#include <cstdint>

#define BB 16
#define QL 16
#define DD 256
#define NH 4
#define HD 64
#define PLEN 512
#define GLEN 16384
#define MAXS 32
#define GM (BB * GLEN)      // 262144
#define PM (BB * PLEN)      // 8192
#define SSTR 132

// ------- scratch (device globals; K/V = 4 head-major planes, tile-swizzled) -
__device__ __half g_kh_g[(size_t)GM * DD];
__device__ __half g_vh_g[(size_t)GM * DD];
__device__ __half g_kh_p[PM * DD];
__device__ __half g_vh_p[PM * DD];
__device__ __half g_wkv_h[2][512 * DD];
__device__ float g_mem[2][BB * QL * DD];
__device__ float g_hq[BB * QL * DD];
__device__ float g_vec[BB * QL * DD];
__device__ float g_ao[BB * QL * DD];
__device__ float g_pacc[BB * NH * MAXS * QL * HD];
__device__ float g_pm[BB * NH * MAXS * QL];
__device__ float g_pl[BB * NH * MAXS * QL];

// ------------------------- fast exp on FMA pipe -----------------------------
__device__ __forceinline__ float fexp(float x) {
    float y = x * 1.4426950408889634f;
    y = fmaxf(y, -125.0f);
    float n = rintf(y);
    float f = y - n;
    float p = 1.3333558146e-3f;
    p = fmaf(p, f, 9.6181291076e-3f);
    p = fmaf(p, f, 5.5504108664e-2f);
    p = fmaf(p, f, 2.4022650696e-1f);
    p = fmaf(p, f, 6.9314718056e-1f);
    p = fmaf(p, f, 1.0f);
    return __int_as_float(((int)n + 127) << 23) * p;
}

// ------------------------- mma / smem / async helpers -----------------------
__device__ __forceinline__ uint32_t smem_u32(const void* p) {
    uint32_t a;
    asm("{ .reg .u64 t; cvta.to.shared.u64 t, %1; cvt.u32.u64 %0, t; }" : "=r"(a) : "l"(p));
    return a;
}
__device__ __forceinline__ void ldm_x4(uint32_t* r, uint32_t addr) {
    asm volatile("ldmatrix.sync.aligned.m8n8.x4.shared.b16 {%0,%1,%2,%3}, [%4];"
                 : "=r"(r[0]), "=r"(r[1]), "=r"(r[2]), "=r"(r[3]) : "r"(addr));
}
__device__ __forceinline__ void ldm_x4_t(uint32_t* r, uint32_t addr) {
    asm volatile("ldmatrix.sync.aligned.m8n8.x4.trans.shared.b16 {%0,%1,%2,%3}, [%4];"
                 : "=r"(r[0]), "=r"(r[1]), "=r"(r[2]), "=r"(r[3]) : "r"(addr));
}
__device__ __forceinline__ void mma16(float* c, const uint32_t* a, const uint32_t* b) {
    asm volatile(
        "mma.sync.aligned.m16n8k16.row.col.f32.f16.f16.f32 "
        "{%0,%1,%2,%3}, {%4,%5,%6,%7}, {%8,%9}, {%0,%1,%2,%3};"
        : "+f"(c[0]), "+f"(c[1]), "+f"(c[2]), "+f"(c[3])
        : "r"(a[0]), "r"(a[1]), "r"(a[2]), "r"(a[3]), "r"(b[0]), "r"(b[1]));
}
__device__ __forceinline__ void cp_a16(uint32_t s, const void* g) {
    asm volatile("cp.async.cg.shared.global [%0], [%1], 16;" :: "r"(s), "l"(g));
}
#define CP_COMMIT() asm volatile("cp.async.commit_group;" ::: "memory")
#define CP_WAIT0()  asm volatile("cp.async.wait_group 0;" ::: "memory")
#define CP_WAIT1()  asm volatile("cp.async.wait_group 1;" ::: "memory")

#define MBAR_INIT(a, c) \
    asm volatile("mbarrier.init.shared.b64 [%0], %1;" :: "r"((uint32_t)(a)), "r"((uint32_t)(c)) : "memory")
#define MBAR_EXPECT_TX(a, n) \
    asm volatile("mbarrier.arrive.expect_tx.shared.b64 _, [%0], %1;" \
                 :: "r"((uint32_t)(a)), "r"((uint32_t)(n)) : "memory")
#define MBAR_WAIT(a, par) do {                                                    \
    uint32_t _m = (uint32_t)(a); uint32_t _p = (uint32_t)(par); uint32_t _d;      \
    asm volatile("{\n\t.reg .pred p;\n\t"                                         \
        "mbarrier.try_wait.parity.acquire.cta.shared::cta.b64 p, [%1], %2;\n\t"   \
        "selp.b32 %0, 1, 0, p;\n\t}" : "=r"(_d) : "r"(_m), "r"(_p) : "memory");   \
    if (!_d) {                                                                    \
        asm volatile("{\n\t.reg .pred P1;\n\tWL_%=:\n\t"                          \
        "mbarrier.try_wait.parity.acquire.cta.shared::cta.b64 P1, [%0], %1, 0x989680;\n\t" \
        "@P1 bra.uni WD_%=;\n\tbra.uni WL_%=;\n\tWD_%=:\n\t}"                     \
        :: "r"(_m), "r"(_p) : "memory");                                          \
    } } while (0)
__device__ __forceinline__ void cp_bulk(uint32_t sdst, const void* gsrc,
                                        uint32_t bytes, uint32_t mbar) {
    asm volatile(
        "cp.async.bulk.shared::cluster.global.mbarrier::complete_tx::bytes "
        "[%0], [%1], %2, [%3];"
        :: "r"(sdst), "l"(gsrc), "r"(bytes), "r"(mbar) : "memory");
}

__device__ __forceinline__ uint32_t packh2(float a, float b) {
    __half2 h = __floats2half2_rn(a, b);
    return *(uint32_t*)&h;
}

// ------------------------- weight convert (transposed, concat K|V) ----------
__global__ void __launch_bounds__(256) split_wkv(const float* __restrict__ Wk,
                                                 const float* __restrict__ Wv,
                                                 __half* __restrict__ Th) {
    int n = blockIdx.x, k = threadIdx.x;
    const float* W = (n < 256) ? Wk : Wv;
    Th[(size_t)n * DD + k] = __float2half_rn(W[(size_t)k * DD + (n & 255)]);
}

// ------- mma GEMM v4: A-panel resident, N-loop in block, cp.async B ---------
// Epilogue writes head-major planes PRE-SWIZZLED per 128-row tile:
//   half index = (head*Mrows + row)*64 + ((d>>3 ^ (row&7))<<3) + (d&7)
#define A_BYTES 65536
#define BSTG 10240
#define KV_SMEM (A_BYTES + 2 * BSTG)   // 86016

__global__ void __launch_bounds__(256) gemm_kv(
    const float* __restrict__ X, const __half* __restrict__ Bhp,
    __half* __restrict__ Kh, __half* __restrict__ Vh, int Mrows) {
    extern __shared__ char smk[];
    uint32_t uA = smem_u32(smk);
    uint32_t uB = uA + A_BYTES;

    int t = threadIdx.x;
    int wid = t >> 5, lane = t & 31;
    int wm = (wid & 3) * 32;
    int wn = (wid >> 2) * 64;
    size_t m0 = (size_t)blockIdx.x * 128;
    int q = lane >> 3, r8 = lane & 7;

#pragma unroll 8
    for (int u = 0; u < 32; u++) {
        int f = t + 256 * u;
        int row = f >> 6, c = f & 63;
        float4 v = *(const float4*)(X + (m0 + row) * DD + c * 4);
        uint32_t off = row * 512 + (((c >> 1) ^ (row & 7)) << 4) + (c & 1) * 8;
        *(uint2*)(smk + off) = make_uint2(packh2(v.x, v.y), packh2(v.z, v.w));
    }
    __syncthreads();

    for (int nb = 0; nb < 4; nb++) {
        int n0 = nb * 128;
        float acc[2][8][4];
#pragma unroll
        for (int i = 0; i < 2; i++)
#pragma unroll
            for (int j = 0; j < 8; j++)
#pragma unroll
                for (int e = 0; e < 4; e++) acc[i][j][e] = 0.f;

#pragma unroll
        for (int u = 0; u < 2; u++) {
            int f = t + 256 * u;
            int row = f >> 2, c = f & 3;
            cp_a16(uB + row * 80 + c * 16, Bhp + (size_t)(n0 + row) * DD + c * 8);
        }
        CP_COMMIT();

        for (int c = 0; c < 8; c++) {
            uint32_t curB = uB + (c & 1) * BSTG;
            __syncthreads();
            if (c + 1 < 8) {
                int k0n = (c + 1) * 32;
                uint32_t nxtB = uB + ((c + 1) & 1) * BSTG;
#pragma unroll
                for (int u = 0; u < 2; u++) {
                    int f = t + 256 * u;
                    int row = f >> 2, cc = f & 3;
                    cp_a16(nxtB + row * 80 + cc * 16,
                           Bhp + (size_t)(n0 + row) * DD + k0n + cc * 8);
                }
                CP_COMMIT();
                CP_WAIT1();
            } else {
                CP_WAIT0();
            }
            __syncthreads();

            int k0 = c * 32;
#pragma unroll
            for (int s = 0; s < 2; s++) {
                int kk = k0 + s * 16;
                uint32_t aH[2][4], bH[8][2];
#pragma unroll
                for (int i = 0; i < 2; i++) {
                    int row = wm + i * 16 + (q & 1) * 8 + r8;
                    int col = kk + (q >> 1) * 8;
                    uint32_t off = row * 512 + ((((uint32_t)col >> 3) ^ (row & 7)) << 4);
                    ldm_x4(aH[i], uA + off);
                }
#pragma unroll
                for (int p = 0; p < 4; p++) {
                    int n = wn + p * 16 + (q >> 1) * 8 + r8;
                    int col = s * 16 + (q & 1) * 8;
                    uint32_t rh[4];
                    ldm_x4(rh, curB + (uint32_t)(n * 40 + col) * 2);
                    bH[2 * p][0] = rh[0]; bH[2 * p][1] = rh[1];
                    bH[2 * p + 1][0] = rh[2]; bH[2 * p + 1][1] = rh[3];
                }
#pragma unroll
                for (int i = 0; i < 2; i++)
#pragma unroll
                    for (int j = 0; j < 8; j++)
                        mma16(acc[i][j], aH[i], bH[j]);
            }
        }

        __half* Dst = (n0 < 256) ? Kh : Vh;
        int cbase = n0 & 255;
#pragma unroll
        for (int i = 0; i < 2; i++) {
            int r0 = wm + i * 16 + (lane >> 2);
#pragma unroll
            for (int j = 0; j < 8; j++) {
                int cc = cbase + wn + j * 8 + (lane & 3) * 2;
                int d = cc & 63;
                int sw = ((((d >> 3) ^ (r0 & 7))) << 3) + (d & 7);
                __half* dp = Dst + ((size_t)(cc >> 6) * Mrows + m0 + r0) * HD + sw;
                *(uint32_t*)dp = packh2(acc[i][j][0], acc[i][j][1]);
                *(uint32_t*)(dp + 8 * HD) = packh2(acc[i][j][2], acc[i][j][3]);
            }
        }
    }
}

// ------------------------- mean pooling: graph -> mem0 ----------------------
__global__ void __launch_bounds__(256) pool_kernel(const float* __restrict__ graph,
                                                   float* __restrict__ mem0) {
    int bm = blockIdx.x;
    int d = threadIdx.x;
    const float* src = graph + (size_t)bm * 1024 * DD + d;
    float s0 = 0.f, s1 = 0.f, s2 = 0.f, s3 = 0.f;
    for (int r = 0; r < 1024; r += 4) {
        s0 += src[(size_t)(r + 0) * DD];
        s1 += src[(size_t)(r + 1) * DD];
        s2 += src[(size_t)(r + 2) * DD];
        s3 += src[(size_t)(r + 3) * DD];
    }
    mem0[(size_t)bm * DD + d] = (s0 + s1 + s2 + s3) * (1.0f / 1024.0f);
}

// ---------------- small GEMM: O[256,256] = X @ W, grid (16,16) --------------
__global__ void __launch_bounds__(256) gemm_small(const float* __restrict__ X,
                                                  const float* __restrict__ W,
                                                  float* __restrict__ O) {
    __shared__ float Xs[16][256];
    int t = threadIdx.x;
    int r0 = blockIdx.y * 16, n0 = blockIdx.x * 16;
#pragma unroll
    for (int u = 0; u < 4; u++) {
        int f = t + 256 * u;
        int row = f >> 6, c4 = (f & 63) << 2;
        *(float4*)&Xs[row][c4] = *(const float4*)(X + (size_t)(r0 + row) * DD + c4);
    }
    __syncthreads();
    int col = n0 + (t & 15), lr = t >> 4;
    float a0 = 0.f, a1 = 0.f, a2 = 0.f, a3 = 0.f;
#pragma unroll 8
    for (int k = 0; k < 256; k += 4) {
        a0 = fmaf(Xs[lr][k + 0], W[(size_t)(k + 0) * DD + col], a0);
        a1 = fmaf(Xs[lr][k + 1], W[(size_t)(k + 1) * DD + col], a1);
        a2 = fmaf(Xs[lr][k + 2], W[(size_t)(k + 2) * DD + col], a2);
        a3 = fmaf(Xs[lr][k + 3], W[(size_t)(k + 3) * DD + col], a3);
    }
    O[(size_t)(r0 + lr) * DD + col] = (a0 + a1) + (a2 + a3);
}

// ------ flash attention v8: cp.async.bulk tile loads, mbarrier pipeline -----
#define STAGE_BYTES 32768
#define ATT_SMEM 74720

__global__ void __launch_bounds__(256) attn_tc4(
    const float* __restrict__ hq,
    const __half* __restrict__ Kh, const __half* __restrict__ Vh,
    const int* __restrict__ mask, int klen, int kps) {
    extern __shared__ char sm[];
    float* Sst = (float*)(sm + 65536);
    float* rowM = (float*)(sm + 73984);
    float* rowL = (float*)(sm + 74048);
    float* rowS = (float*)(sm + 74112);
    int* mk = (int*)(sm + 74176);
    uint32_t uBase = smem_u32(sm);
    uint32_t uMbar = uBase + 74688;          // 2 mbarriers (8B each)

    int t = threadIdx.x;
    int w = t >> 5, lane = t & 31;
    int g = lane >> 2, tig = lane & 3;
    int q2 = lane >> 3, r8 = lane & 7;
    int split = blockIdx.x, h = blockIdx.y, b = blockIdx.z;
    int key0 = split * kps;
    int ntiles = kps >> 7;
    size_t prow = ((size_t)(h * BB + b)) * klen;

    {
        int r = t >> 4, c4 = (t & 15) << 2;
        *(float4*)&Sst[r * 64 + c4] =
            *(const float4*)(hq + (size_t)(b * QL + r) * DD + h * HD + c4);
    }
    if (t < 16) { rowM[t] = -3e38f; rowL[t] = 0.f; rowS[t] = 0.f; }
    if (t == 0) { MBAR_INIT(uMbar, 1); MBAR_INIT(uMbar + 8, 1); }
    __syncthreads();

    // prologue: tile 0 -> stage 0
    if (t == 0) {
        MBAR_EXPECT_TX(uMbar, 2 * 16384);
        cp_bulk(uBase, Kh + (prow + key0) * HD, 16384, uMbar);
        cp_bulk(uBase + 16384, Vh + (prow + key0) * HD, 16384, uMbar);
    }

    // Q fragments: single fp16 plane
    uint32_t qh[4][4];
#pragma unroll
    for (int s = 0; s < 4; s++) {
        int cb = s * 16 + tig * 2;
        qh[s][0] = packh2(Sst[g * 64 + cb], Sst[g * 64 + cb + 1]);
        qh[s][1] = packh2(Sst[(g + 8) * 64 + cb], Sst[(g + 8) * 64 + cb + 1]);
        qh[s][2] = packh2(Sst[g * 64 + cb + 8], Sst[g * 64 + cb + 9]);
        qh[s][3] = packh2(Sst[(g + 8) * 64 + cb + 8], Sst[(g + 8) * 64 + cb + 9]);
    }

    float acc[4] = {0.f, 0.f, 0.f, 0.f};
    uint32_t* SW = (uint32_t*)Sst;

    for (int kt = 0; kt < ntiles; kt++) {
        uint32_t stage = uBase + (kt & 1) * STAGE_BYTES;
        int k0 = key0 + (kt << 7);
        __syncthreads();   // all warps done reading the buddy stage (tile kt-1)
        if (kt + 1 < ntiles && t == 0) {
            uint32_t mb = uMbar + 8 * ((kt + 1) & 1);
            uint32_t sdst = uBase + ((kt + 1) & 1) * STAGE_BYTES;
            MBAR_EXPECT_TX(mb, 2 * 16384);
            cp_bulk(sdst, Kh + (prow + k0 + 128) * HD, 16384, mb);
            cp_bulk(sdst + 16384, Vh + (prow + k0 + 128) * HD, 16384, mb);
        }
        MBAR_WAIT(uMbar + 8 * (kt & 1), (kt >> 1) & 1);
        if (t < 128) mk[t] = mask[(size_t)b * klen + k0 + t];

        // ---- QK (1-pass): warp w covers keys [w*16, w*16+16) ----
        float c2[2][4];
#pragma unroll
        for (int j = 0; j < 2; j++)
#pragma unroll
            for (int e = 0; e < 4; e++) c2[j][e] = 0.f;
#pragma unroll
        for (int s = 0; s < 4; s++) {
            int row = w * 16 + (q2 >> 1) * 8 + r8;
            int ch = s * 2 + (q2 & 1);
            uint32_t off = stage + row * 128 + ((ch ^ (row & 7)) << 4);
            uint32_t rh[4];
            ldm_x4(rh, off);
            uint32_t b0h[2] = {rh[0], rh[1]}, b1h[2] = {rh[2], rh[3]};
            mma16(c2[0], qh[s], b0h);
            mma16(c2[1], qh[s], b1h);
        }
#pragma unroll
        for (int j = 0; j < 2; j++) {
            int kc = w * 16 + j * 8 + tig * 2;
            Sst[g * SSTR + kc] = c2[j][0] * 0.125f;
            Sst[g * SSTR + kc + 1] = c2[j][1] * 0.125f;
            Sst[(g + 8) * SSTR + kc] = c2[j][2] * 0.125f;
            Sst[(g + 8) * SSTR + kc + 1] = c2[j][3] * 0.125f;
        }
        __syncthreads();

        // ---- online softmax; pack P fp16 pairs (even words) ----
        {
            int row = t >> 4, sub = t & 15;
            int cb = sub * 8;
            float sv[8];
#pragma unroll
            for (int i = 0; i < 8; i++) sv[i] = Sst[row * SSTR + cb + i];
            float lmax = -3e38f;
#pragma unroll
            for (int i = 0; i < 8; i++)
                if (mk[cb + i]) lmax = fmaxf(lmax, sv[i]);
#pragma unroll
            for (int o = 8; o; o >>= 1) lmax = fmaxf(lmax, __shfl_xor_sync(~0u, lmax, o));
            float oldm = rowM[row];
            float newm = fmaxf(oldm, lmax);
            float pv[8];
            float lsum = 0.f;
#pragma unroll
            for (int i = 0; i < 8; i++) {
                pv[i] = mk[cb + i] ? fexp(sv[i] - newm) : 0.f;
                lsum += pv[i];
            }
#pragma unroll
            for (int o = 8; o; o >>= 1) lsum += __shfl_xor_sync(~0u, lsum, o);
            if (sub == 0) {
                float sc = fexp(oldm - newm);
                rowS[row] = sc;
                rowL[row] = rowL[row] * sc + lsum;
                rowM[row] = newm;
            }
#pragma unroll
            for (int i = 0; i < 8; i += 2)
                SW[row * SSTR + cb + i] = packh2(pv[i], pv[i + 1]);
        }
        __syncthreads();

        // ---- PV (1-pass): warp w covers dims [w*8, w*8+8) ----
        {
            float s0 = rowS[g], s1 = rowS[g + 8];
            acc[0] *= s0; acc[1] *= s0; acc[2] *= s1; acc[3] *= s1;
#pragma unroll
            for (int kb = 0; kb < 4; kb++) {
                int vrow = kb * 32 + q2 * 8 + r8;
                uint32_t voff = stage + 16384 + vrow * 128 + ((w ^ (vrow & 7)) << 4);
                uint32_t v4[4];
                ldm_x4_t(v4, voff);
#pragma unroll
                for (int kh2 = 0; kh2 < 2; kh2++) {
                    int kk = kb * 32 + kh2 * 16;
                    uint32_t ah[4] = {SW[g * SSTR + kk + tig * 2],
                                      SW[(g + 8) * SSTR + kk + tig * 2],
                                      SW[g * SSTR + kk + 8 + tig * 2],
                                      SW[(g + 8) * SSTR + kk + 8 + tig * 2]};
                    uint32_t bh[2] = {v4[2 * kh2], v4[2 * kh2 + 1]};
                    mma16(acc, ah, bh);
                }
            }
        }
    }
    size_t pbase = ((size_t)(b * NH + h) * MAXS + split) * QL;
    float* pa = g_pacc + pbase * HD;
    int cc = w * 8 + tig * 2;
    *(float2*)(pa + (size_t)g * HD + cc) = make_float2(acc[0], acc[1]);
    *(float2*)(pa + (size_t)(g + 8) * HD + cc) = make_float2(acc[2], acc[3]);
    if (t < 16) { g_pm[pbase + t] = rowM[t]; g_pl[pbase + t] = rowL[t]; }
}

// ------------------------- merge split-K partials ---------------------------
__global__ void __launch_bounds__(256) attn_merge(float* __restrict__ vec, int nsplit) {
    __shared__ float w[MAXS][16];
    __shared__ float invL[16];
    int t = threadIdx.x;
    int h = blockIdx.x, b = blockIdx.y;
    size_t base = (size_t)(b * NH + h) * MAXS * QL;
    if (t < 16) {
        float M = -3e38f;
        for (int s = 0; s < nsplit; s++) M = fmaxf(M, g_pm[base + s * QL + t]);
        float L = 0.f;
        for (int s = 0; s < nsplit; s++) {
            float ww = fexp(g_pm[base + s * QL + t] - M);
            w[s][t] = ww;
            L += g_pl[base + s * QL + t] * ww;
        }
        invL[t] = 1.f / L;
    }
    __syncthreads();
    int r = t >> 4, c4 = (t & 15) << 2;
    float ox = 0.f, oy = 0.f, oz = 0.f, ow = 0.f;
    for (int s = 0; s < nsplit; s++) {
        float ww = w[s][r];
        float4 a = *(const float4*)(g_pacc + (base + s * QL + r) * HD + c4);
        ox = fmaf(a.x, ww, ox); oy = fmaf(a.y, ww, oy);
        oz = fmaf(a.z, ww, oz); ow = fmaf(a.w, ww, ow);
    }
    float il = invL[r];
    *(float4*)(vec + (size_t)(b * QL + r) * DD + h * HD + c4) =
        make_float4(ox * il, oy * il, oz * il, ow * il);
}

// ------------------------- gate + residual ----------------------------------
__global__ void __launch_bounds__(256) gate_kernel(
    const float* __restrict__ mem, const float* __restrict__ ao,
    const float* __restrict__ Wg, const float* __restrict__ bg,
    float* __restrict__ out) {
    __shared__ float xs[512];
    int row = blockIdx.x;
    int c = threadIdx.x;
    xs[c] = mem[(size_t)row * DD + c];
    xs[256 + c] = ao[(size_t)row * DD + c];
    __syncthreads();
    float s0 = 0.f, s1 = 0.f, s2 = 0.f, s3 = 0.f;
#pragma unroll 4
    for (int k = 0; k < 512; k += 4) {
        float4 x = *(float4*)&xs[k];
        s0 = fmaf(x.x, Wg[(size_t)(k + 0) * DD + c], s0);
        s1 = fmaf(x.y, Wg[(size_t)(k + 1) * DD + c], s1);
        s2 = fmaf(x.z, Wg[(size_t)(k + 2) * DD + c], s2);
        s3 = fmaf(x.w, Wg[(size_t)(k + 3) * DD + c], s3);
    }
    float sum = (s0 + s1) + (s2 + s3) + bg[c];
    float gate = 1.f / (1.f + fexp(-sum));
    out[(size_t)row * DD + c] = gate * xs[c] + (1.f - gate) * xs[256 + c];
}

// ------------------------- launch -------------------------------------------
extern "C" void kernel_launch(void* const* d_in, const int* in_sizes, int n_in,
                              void* d_out, int out_size) {
    const float* pattern = (const float*)d_in[0];
    const float* graph = (const float*)d_in[1];
    const int* pmask = (const int*)d_in[2];
    const int* gmask = (const int*)d_in[3];
    const float* pW[6];
    const float* gW[6];
    for (int i = 0; i < 6; i++) pW[i] = (const float*)d_in[4 + i];
    for (int i = 0; i < 6; i++) gW[i] = (const float*)d_in[10 + i];
    float* out = (float*)d_out;

    float *memb, *hq, *vec, *ao;
    __half *khg, *vhg, *khp, *vhp, *wh;
    cudaGetSymbolAddress((void**)&memb, g_mem);
    cudaGetSymbolAddress((void**)&hq, g_hq);
    cudaGetSymbolAddress((void**)&vec, g_vec);
    cudaGetSymbolAddress((void**)&ao, g_ao);
    cudaGetSymbolAddress((void**)&khg, g_kh_g);
    cudaGetSymbolAddress((void**)&vhg, g_vh_g);
    cudaGetSymbolAddress((void**)&khp, g_kh_p);
    cudaGetSymbolAddress((void**)&vhp, g_vh_p);
    cudaGetSymbolAddress((void**)&wh, g_wkv_h);
    float* mem0 = memb;
    float* mem1 = memb + BB * QL * DD;

    cudaFuncSetAttribute(attn_tc4, cudaFuncAttributeMaxDynamicSharedMemorySize,
                         ATT_SMEM);
    cudaFuncSetAttribute(gemm_kv, cudaFuncAttributeMaxDynamicSharedMemorySize,
                         KV_SMEM);

    pool_kernel<<<256, 256>>>(graph, mem0);                                   // 1
    split_wkv<<<512, 256>>>(gW[1], gW[2], wh + 512 * DD);                     // 2
    split_wkv<<<512, 256>>>(pW[1], pW[2], wh);                                // 3
    gemm_kv<<<GM / 128, 256, KV_SMEM>>>(graph, wh + 512 * DD, khg, vhg, GM);  // 4 (profiled)
    gemm_kv<<<PM / 128, 256, KV_SMEM>>>(pattern, wh, khp, vhp, PM);           // 5

    float* cur = mem0;
    float* other = mem1;
    for (int it = 0; it < 3; it++) {
        for (int ph = 0; ph < 2; ph++) {
            const float* const* W = ph ? gW : pW;
            const __half* kh = ph ? khg : khp;
            const __half* vh = ph ? vhg : vhp;
            const int* mask = ph ? gmask : pmask;
            int klen = ph ? GLEN : PLEN;
            int splits = ph ? 16 : 4;
            int kps = klen / splits;

            gemm_small<<<dim3(16, 16), 256>>>(cur, W[0], hq);
            attn_tc4<<<dim3(splits, NH, BB), 256, ATT_SMEM>>>(hq, kh, vh,
                                                              mask, klen, kps);
            attn_merge<<<dim3(NH, BB), 256>>>(vec, splits);
            gemm_small<<<dim3(16, 16), 256>>>(vec, W[3], ao);

            bool last = (it == 2 && ph == 1);
            float* dst = last ? out : other;
            gate_kernel<<<256, 256>>>(cur, ao, W[4], W[5], dst);
            other = cur;
            cur = dst;
        }
    }
}